// round 4
// baseline (speedup 1.0000x reference)
#include <cuda_runtime.h>

#define MAXN 20000
#define DIN  128
#define DHID 256
#define DDNS 128
#define NYB  148          // k_y grid size (partial buffers)

// Persistent scratch. RED-accumulators are zero at module load and re-zeroed
// by this run AFTER their last consumption, so every replay sees clean state.
__device__ float g_de[MAXN];            // edge-accumulated degree (no self-loop)
__device__ float g_se[MAXN];            // edge part of s
__device__ float g_te[MAXN];            // edge part of t
__device__ float g_ypart[NYB][DIN];     // per-block partial y (pure stores)
__device__ float g_spart[NYB];          // per-block partial sum_s (pure stores)
__device__ float g_sum_s;               // plain store by k_u block 0
__device__ float g_u[DHID];             // RED accum, zeroed in k_out
__device__ float g_g[DHID];             // RED accum, zeroed in k_out
__device__ float g_z[DDNS];             // RED accum, zeroed in k_out

// ---------------------------------------------------------------------------
// Edge pass 1: de[c] += w
__global__ void k_deg(const int* __restrict__ col, const float* __restrict__ w, int e) {
    int i = blockIdx.x * blockDim.x + threadIdx.x;
    if (i < e) atomicAdd(&g_de[col[i]], w[i]);
}

// Edge pass 2: se[r] += w * rsqrt(1 + de[c])
__global__ void k_s(const int* __restrict__ row, const int* __restrict__ col,
                    const float* __restrict__ w, int e) {
    int i = blockIdx.x * blockDim.x + threadIdx.x;
    if (i < e) {
        float de = __ldg(&g_de[col[i]]);
        atomicAdd(&g_se[row[i]], w[i] * rsqrtf(1.0f + de));
    }
}

// Edge pass 3: te[r] += w * q[c],  q = di*(di*se + di^2),  di = rsqrt(1+de)
__global__ void k_t(const int* __restrict__ row, const int* __restrict__ col,
                    const float* __restrict__ w, int e) {
    int i = blockIdx.x * blockDim.x + threadIdx.x;
    if (i < e) {
        int c = col[i];
        float de = __ldg(&g_de[c]);
        float se = __ldg(&g_se[c]);
        float di = rsqrtf(1.0f + de);
        float s  = di * se + di * di;
        atomicAdd(&g_te[row[i]], w[i] * di * s);
    }
}

// k_y: per-block partial of y[d] = sum_r t[r]*X[r,d] and sum_s.
// t[r] = di*te + di^2*s,  s = di*se + di^2. No atomics: plain stores to
// g_ypart/g_spart. Re-zeroes de/se/te after their last read.
__global__ void __launch_bounds__(256) k_y(const float* __restrict__ X, int n) {
    int tid  = threadIdx.x;
    int lane = tid & 31;
    int wid  = tid >> 5;                           // 8 warps
    int chunk = (n + gridDim.x - 1) / gridDim.x;
    int start = blockIdx.x * chunk;
    int end   = min(n, start + chunk);

    float4 acc = make_float4(0.f, 0.f, 0.f, 0.f);
    float  ssum = 0.0f;
    #pragma unroll 2
    for (int r = start + wid; r < end; r += 8) {
        float de = g_de[r];
        float se = g_se[r];
        float te = g_te[r];
        float di = rsqrtf(1.0f + de);
        float s  = di * se + di * di;
        float tv = di * te + di * di * s;
        if (lane == 0) {
            g_de[r] = 0.0f; g_se[r] = 0.0f; g_te[r] = 0.0f;
            ssum += s;
        }
        float4 x = __ldg((const float4*)(X + (size_t)r * DIN) + lane);
        acc.x += tv * x.x;
        acc.y += tv * x.y;
        acc.z += tv * x.z;
        acc.w += tv * x.w;
    }

    __shared__ float sacc[8][DIN];
    __shared__ float swsum[8];
    sacc[wid][lane * 4 + 0] = acc.x;
    sacc[wid][lane * 4 + 1] = acc.y;
    sacc[wid][lane * 4 + 2] = acc.z;
    sacc[wid][lane * 4 + 3] = acc.w;
    if (lane == 0) swsum[wid] = ssum;
    __syncthreads();
    if (tid < DIN) {
        float v = 0.0f;
        #pragma unroll
        for (int k = 0; k < 8; k++) v += sacc[k][tid];
        g_ypart[blockIdx.x][tid] = v;
    }
    if (tid == DIN) {
        float v = 0.0f;
        #pragma unroll
        for (int k = 0; k < 8; k++) v += swsum[k];
        g_spart[blockIdx.x] = v;
    }
}

// k_u: u[j] = sum_d y[d]*W1[d,j]  (split over d: 16 blocks x 8 d's).
// First reduces y[d0..d0+7] from g_ypart. Block 0 also reduces g_spart -> g_sum_s.
__global__ void __launch_bounds__(256) k_u(const float* __restrict__ W1) {
    __shared__ float sy[8];
    int tid = threadIdx.x;
    int lane = tid & 31;
    int wid  = tid >> 5;
    int d0 = blockIdx.x * 8;

    // warp w reduces y[d0+w] over NYB partials
    {
        float v = 0.0f;
        for (int b = lane; b < NYB; b += 32) v += g_ypart[b][d0 + wid];
        #pragma unroll
        for (int o = 16; o > 0; o >>= 1) v += __shfl_down_sync(0xffffffffu, v, o);
        if (lane == 0) sy[wid] = v;
    }
    if (blockIdx.x == 0 && wid == 0) {
        float v = 0.0f;
        for (int b = lane; b < NYB; b += 32) v += g_spart[b];
        #pragma unroll
        for (int o = 16; o > 0; o >>= 1) v += __shfl_down_sync(0xffffffffu, v, o);
        if (lane == 0) g_sum_s = v;
    }
    __syncthreads();

    float p = 0.0f;
    #pragma unroll
    for (int d = 0; d < 8; d++) p += sy[d] * __ldg(&W1[(d0 + d) * DHID + tid]);
    atomicAdd(&g_u[tid], p);
}

// k_g: g_raw[j] = sum_k (u[k] + sum_s*b1[k]) * W2[k,j]  (split over k: 32 x 8)
__global__ void __launch_bounds__(256) k_g(const float* __restrict__ W2,
                                           const float* __restrict__ b1) {
    __shared__ float su[8];
    int tid = threadIdx.x;
    int k0 = blockIdx.x * 8;
    if (tid < 8) su[tid] = g_u[k0 + tid] + g_sum_s * __ldg(&b1[k0 + tid]);
    __syncthreads();

    float p = 0.0f;
    #pragma unroll
    for (int k = 0; k < 8; k++) p += su[k] * __ldg(&W2[(k0 + k) * DHID + tid]);
    atomicAdd(&g_g[tid], p);
}

// k_z: z_raw[i] = sum_j (g_raw[j]/n + b2[j]) * Wd1[j,i]  (split over j: 32 x 8)
__global__ void __launch_bounds__(128) k_z(const float* __restrict__ Wd1,
                                           const float* __restrict__ b2, float invn) {
    __shared__ float sg[8];
    int tid = threadIdx.x;
    int j0 = blockIdx.x * 8;
    if (tid < 8) sg[tid] = g_g[j0 + tid] * invn + __ldg(&b2[j0 + tid]);
    __syncthreads();

    float p = 0.0f;
    #pragma unroll
    for (int j = 0; j < 8; j++) p += sg[j] * __ldg(&Wd1[(j0 + j) * DDNS + tid]);
    atomicAdd(&g_z[tid], p);
}

// k_out: z = relu(z_raw + bd1); logits = z*Wd2 + bd2; softmax; re-zero scratch.
__global__ void __launch_bounds__(128) k_out(const float* __restrict__ bd1,
                                             const float* __restrict__ Wd2,
                                             const float* __restrict__ bd2,
                                             float* __restrict__ out) {
    __shared__ float sp0[4], sp1[4];
    int tid = threadIdx.x;
    int lane = tid & 31, wid = tid >> 5;

    float zr = g_z[tid] + bd1[tid];
    float z  = zr > 0.0f ? zr : 0.0f;
    float p0 = z * __ldg(&Wd2[tid * 2 + 0]);
    float p1 = z * __ldg(&Wd2[tid * 2 + 1]);
    #pragma unroll
    for (int o = 16; o > 0; o >>= 1) {
        p0 += __shfl_down_sync(0xffffffffu, p0, o);
        p1 += __shfl_down_sync(0xffffffffu, p1, o);
    }
    if (lane == 0) { sp0[wid] = p0; sp1[wid] = p1; }
    __syncthreads();

    if (tid == 0) {
        float l0 = bd2[0] + sp0[0] + sp0[1] + sp0[2] + sp0[3];
        float l1 = bd2[1] + sp1[0] + sp1[1] + sp1[2] + sp1[3];
        float m  = fmaxf(l0, l1);
        float e0 = __expf(l0 - m);
        float e1 = __expf(l1 - m);
        float inv = 1.0f / (e0 + e1);
        out[0] = e0 * inv;
        out[1] = e1 * inv;
    }
    // re-zero RED accumulators for next replay
    g_z[tid] = 0.0f;
    g_u[tid] = 0.0f; g_u[tid + 128] = 0.0f;
    g_g[tid] = 0.0f; g_g[tid + 128] = 0.0f;
}

// ---------------------------------------------------------------------------
extern "C" void kernel_launch(void* const* d_in, const int* in_sizes, int n_in,
                              void* d_out, int out_size) {
    const float* X   = (const float*)d_in[0];
    const int*   ei  = (const int*)  d_in[1];
    const float* w   = (const float*)d_in[2];
    const float* W1  = (const float*)d_in[3];
    const float* b1  = (const float*)d_in[4];
    const float* W2  = (const float*)d_in[5];
    const float* b2  = (const float*)d_in[6];
    const float* Wd1 = (const float*)d_in[7];
    const float* bd1 = (const float*)d_in[8];
    const float* Wd2 = (const float*)d_in[9];
    const float* bd2 = (const float*)d_in[10];
    float* out = (float*)d_out;

    int n = in_sizes[0] / DIN;        // 20000
    int e = in_sizes[2];              // 640000
    const int* row = ei;
    const int* col = ei + e;

    int nb_e = (e + 255) / 256;       // 2500 blocks — proven edge shape

    k_deg<<<nb_e, 256>>>(col, w, e);
    k_s  <<<nb_e, 256>>>(row, col, w, e);
    k_t  <<<nb_e, 256>>>(row, col, w, e);
    k_y  <<<NYB,  256>>>(X, n);
    k_u  <<<16,   256>>>(W1);
    k_g  <<<32,   256>>>(W2, b1);
    k_z  <<<32,   128>>>(Wd1, b2, 1.0f / (float)n);
    k_out<<<1,    128>>>(bd1, Wd2, bd2, out);
}

// round 5
// speedup vs baseline: 1.7546x; 1.7546x over previous
#include <cuda_runtime.h>

#define MAXN 20000
#define DIN  128
#define DHID 256
#define DDNS 128
#define NBLK 304
#define NTHR 256

// Persistent scratch. All accumulators zero at module load; each run re-zeroes
// everything it dirties AFTER last consumption -> replays see clean state.
__device__ float g_de[MAXN];            // RED: degree (no self-loop)
__device__ float g_se[MAXN];            // RED: edge part of s
__device__ float g_te[MAXN];            // RED: edge part of t
__device__ float g_ypart[NBLK][DIN];    // per-block partial y (plain stores)
__device__ float g_spart[NBLK];         // per-block partial sum_s
__device__ float g_sum_s;               // plain store by k_u block 0
__device__ float g_u[DHID];             // RED accum, zeroed in k_out
__device__ float g_g[DHID];             // RED accum, zeroed in k_out
__device__ float g_z[DDNS];             // RED accum, zeroed in k_out
__device__ unsigned g_count;            // barrier arrive count (self-resetting)
__device__ unsigned g_gen;              // barrier generation (monotonic, ok)

// Software grid barrier: all NBLK blocks are resident by construction
// (2 CTAs/SM of 256 threads, ~40 regs, tiny smem).
__device__ __forceinline__ void grid_sync() {
    __syncthreads();
    if (threadIdx.x == 0) {
        __threadfence();                       // make my REDs visible
        unsigned gen = g_gen;
        if (atomicAdd(&g_count, 1u) == NBLK - 1u) {
            g_count = 0u;
            __threadfence();
            atomicExch(&g_gen, gen + 1u);      // release
        } else {
            while (atomicAdd(&g_gen, 0u) == gen) __nanosleep(64);
            __threadfence();                   // acquire
        }
    }
    __syncthreads();
}

// ---------------------------------------------------------------------------
// Fused: 3 edge phases + weighted feature reduction y = X^T t, sum_s.
__global__ void __launch_bounds__(NTHR, 2)
k_main(const float* __restrict__ X,
       const int* __restrict__ row, const int* __restrict__ col,
       const float* __restrict__ w, int e, int n, int chunk) {
    const int t0     = blockIdx.x * NTHR + threadIdx.x;
    const int stride = NBLK * NTHR;

    // Phase 1: de[c] += w
    for (int i = t0; i < e; i += stride)
        atomicAdd(&g_de[col[i]], w[i]);
    grid_sync();

    // Phase 2: se[r] += w * rsqrt(1 + de[c])
    for (int i = t0; i < e; i += stride) {
        float de = __ldg(&g_de[col[i]]);
        atomicAdd(&g_se[row[i]], w[i] * rsqrtf(1.0f + de));
    }
    grid_sync();

    // Phase 3: te[r] += w * q[c],  q = di*(di*se + di^2)
    for (int i = t0; i < e; i += stride) {
        int c = col[i];
        float de = __ldg(&g_de[c]);
        float se = __ldg(&g_se[c]);
        float di = rsqrtf(1.0f + de);
        float s  = di * se + di * di;
        atomicAdd(&g_te[row[i]], w[i] * di * s);
    }
    grid_sync();

    // Phase 4 (column-parallel, R1-proven shape):
    // y[d] += sum_r t[r] * X[r,d];  t = di*te + di^2*s;  s = di*se + di^2.
    // 256 threads: d = tid&127, half = tid>>7 splits the k-loop in two.
    __shared__ float st[128];
    __shared__ float sacc[2][DIN];
    __shared__ float sred[8];

    const int tid  = threadIdx.x;
    const int d    = tid & 127;
    const int half = tid >> 7;
    const int start = blockIdx.x * chunk;
    const int end   = min(n, start + chunk);

    float acc  = 0.0f;
    float ssum = 0.0f;

    for (int base = start; base < end; base += 128) {
        int m = min(128, end - base);
        __syncthreads();
        if (tid < m) {
            int r = base + tid;
            float de = g_de[r];
            float se = g_se[r];
            float te = g_te[r];
            float di = rsqrtf(1.0f + de);
            float s  = di * se + di * di;
            st[tid] = di * te + di * di * s;
            ssum += s;
            g_de[r] = 0.0f; g_se[r] = 0.0f; g_te[r] = 0.0f;  // clean for next run
        }
        __syncthreads();
        #pragma unroll 8
        for (int k = half; k < m; k += 2)
            acc += st[k] * __ldg(X + (size_t)(base + k) * DIN + d);
    }

    sacc[half][d] = acc;
    __syncthreads();
    if (tid < DIN)
        g_ypart[blockIdx.x][tid] = sacc[0][tid] + sacc[1][tid];

    // block-reduce ssum (threads >= 128 contribute 0)
    int lane = tid & 31, wid = tid >> 5;
    #pragma unroll
    for (int o = 16; o > 0; o >>= 1) ssum += __shfl_down_sync(0xffffffffu, ssum, o);
    if (lane == 0) sred[wid] = ssum;
    __syncthreads();
    if (wid == 0) {
        float v = (lane < 8) ? sred[lane] : 0.0f;
        #pragma unroll
        for (int o = 4; o > 0; o >>= 1) v += __shfl_down_sync(0xffffffffu, v, o);
        if (lane == 0) g_spart[blockIdx.x] = v;
    }
}

// ---------------------------------------------------------------------------
// k_u: u[j] = sum_d y[d]*W1[d,j]  (16 blocks x 8 d's). Block 0 also reduces sum_s.
__global__ void __launch_bounds__(256) k_u(const float* __restrict__ W1) {
    __shared__ float sy[8];
    int tid = threadIdx.x;
    int lane = tid & 31;
    int wid  = tid >> 5;
    int d0 = blockIdx.x * 8;

    {
        float v = 0.0f;
        for (int b = lane; b < NBLK; b += 32) v += g_ypart[b][d0 + wid];
        #pragma unroll
        for (int o = 16; o > 0; o >>= 1) v += __shfl_down_sync(0xffffffffu, v, o);
        if (lane == 0) sy[wid] = v;
    }
    if (blockIdx.x == 0 && wid == 0) {
        float v = 0.0f;
        for (int b = lane; b < NBLK; b += 32) v += g_spart[b];
        #pragma unroll
        for (int o = 16; o > 0; o >>= 1) v += __shfl_down_sync(0xffffffffu, v, o);
        if (lane == 0) g_sum_s = v;
    }
    __syncthreads();

    float p = 0.0f;
    #pragma unroll
    for (int d = 0; d < 8; d++) p += sy[d] * __ldg(&W1[(d0 + d) * DHID + tid]);
    atomicAdd(&g_u[tid], p);
}

// k_g: g_raw[j] = sum_k (u[k] + sum_s*b1[k]) * W2[k,j]   (32 blocks x 8 k's)
__global__ void __launch_bounds__(256) k_g(const float* __restrict__ W2,
                                           const float* __restrict__ b1) {
    __shared__ float su[8];
    int tid = threadIdx.x;
    int k0 = blockIdx.x * 8;
    if (tid < 8) su[tid] = g_u[k0 + tid] + g_sum_s * __ldg(&b1[k0 + tid]);
    __syncthreads();

    float p = 0.0f;
    #pragma unroll
    for (int k = 0; k < 8; k++) p += su[k] * __ldg(&W2[(k0 + k) * DHID + tid]);
    atomicAdd(&g_g[tid], p);
}

// k_z: z_raw[i] = sum_j (g_raw[j]/n + b2[j]) * Wd1[j,i]   (32 blocks x 8 j's)
__global__ void __launch_bounds__(128) k_z(const float* __restrict__ Wd1,
                                           const float* __restrict__ b2, float invn) {
    __shared__ float sg[8];
    int tid = threadIdx.x;
    int j0 = blockIdx.x * 8;
    if (tid < 8) sg[tid] = g_g[j0 + tid] * invn + __ldg(&b2[j0 + tid]);
    __syncthreads();

    float p = 0.0f;
    #pragma unroll
    for (int j = 0; j < 8; j++) p += sg[j] * __ldg(&Wd1[(j0 + j) * DDNS + tid]);
    atomicAdd(&g_z[tid], p);
}

// k_out: z = relu(z_raw + bd1); logits = z*Wd2 + bd2; softmax; re-zero scratch.
__global__ void __launch_bounds__(128) k_out(const float* __restrict__ bd1,
                                             const float* __restrict__ Wd2,
                                             const float* __restrict__ bd2,
                                             float* __restrict__ out) {
    __shared__ float sp0[4], sp1[4];
    int tid = threadIdx.x;
    int lane = tid & 31, wid = tid >> 5;

    float zr = g_z[tid] + bd1[tid];
    float z  = zr > 0.0f ? zr : 0.0f;
    float p0 = z * __ldg(&Wd2[tid * 2 + 0]);
    float p1 = z * __ldg(&Wd2[tid * 2 + 1]);
    #pragma unroll
    for (int o = 16; o > 0; o >>= 1) {
        p0 += __shfl_down_sync(0xffffffffu, p0, o);
        p1 += __shfl_down_sync(0xffffffffu, p1, o);
    }
    if (lane == 0) { sp0[wid] = p0; sp1[wid] = p1; }
    __syncthreads();

    if (tid == 0) {
        float l0 = bd2[0] + sp0[0] + sp0[1] + sp0[2] + sp0[3];
        float l1 = bd2[1] + sp1[0] + sp1[1] + sp1[2] + sp1[3];
        float m  = fmaxf(l0, l1);
        float e0 = __expf(l0 - m);
        float e1 = __expf(l1 - m);
        float inv = 1.0f / (e0 + e1);
        out[0] = e0 * inv;
        out[1] = e1 * inv;
    }
    g_z[tid] = 0.0f;
    g_u[tid] = 0.0f; g_u[tid + 128] = 0.0f;
    g_g[tid] = 0.0f; g_g[tid + 128] = 0.0f;
}

// ---------------------------------------------------------------------------
extern "C" void kernel_launch(void* const* d_in, const int* in_sizes, int n_in,
                              void* d_out, int out_size) {
    const float* X   = (const float*)d_in[0];
    const int*   ei  = (const int*)  d_in[1];
    const float* w   = (const float*)d_in[2];
    const float* W1  = (const float*)d_in[3];
    const float* b1  = (const float*)d_in[4];
    const float* W2  = (const float*)d_in[5];
    const float* b2  = (const float*)d_in[6];
    const float* Wd1 = (const float*)d_in[7];
    const float* bd1 = (const float*)d_in[8];
    const float* Wd2 = (const float*)d_in[9];
    const float* bd2 = (const float*)d_in[10];
    float* out = (float*)d_out;

    int n = in_sizes[0] / DIN;        // 20000
    int e = in_sizes[2];              // 640000
    const int* row = ei;
    const int* col = ei + e;
    int chunk = (n + NBLK - 1) / NBLK;

    k_main<<<NBLK, NTHR>>>(X, row, col, w, e, n, chunk);
    k_u   <<<16,   256>>>(W1);
    k_g   <<<32,   256>>>(W2, b1);
    k_z   <<<32,   128>>>(Wd1, b2, 1.0f / (float)n);
    k_out <<<1,    128>>>(bd1, Wd2, bd2, out);
}